// round 12
// baseline (speedup 1.0000x reference)
#include <cuda_runtime.h>
#include <cuda_fp16.h>
#include <cuda_bf16.h>
#include <mma.h>
#include <cstdint>

using namespace nvcuda;

#define NN 30000
#define NE 480000
#define HID 128
#define F_IN 64
#define F_EDGE 16
#define NCLS 10

typedef unsigned long long ull;

__device__ __forceinline__ ull pack2(float lo, float hi) {
    ull r; asm("mov.b64 %0, {%1, %2};" : "=l"(r) : "f"(lo), "f"(hi)); return r;
}
__device__ __forceinline__ float2 unpack2(ull v) {
    float2 r; asm("mov.b64 {%0, %1}, %2;" : "=f"(r.x), "=f"(r.y) : "l"(v)); return r;
}
__device__ __forceinline__ void fma2(ull& d, ull a, ull b) {
    asm("fma.rn.f32x2 %0, %1, %2, %0;" : "+l"(d) : "l"(a), "l"(b));
}

// ---------------- device scratch ----------------
__device__ __align__(16) __half g_eah[(size_t)NE * HID];
__device__ int   g_srcs[NE];
__device__ int   g_rowptr[NN + 1];
__device__ int   g_cnt[NN];
__device__ __align__(16) float  g_h[NN * HID];
__device__ __align__(16) __half g_ninh[NN * HID];          // fp16 gather + additive table
__device__ __align__(16) __nv_bfloat16 g_zh[NN * HID];
__device__ __align__(16) __nv_bfloat16 g_zl[NN * HID];
__device__ __align__(16) __nv_bfloat16 g_w1h[3 * 256 * 128];   // W1^T hi: (n,k) at n*128+k
__device__ __align__(16) __nv_bfloat16 g_w1l[3 * 256 * 128];
__device__ __align__(16) __nv_bfloat16 g_w2h[3 * 128 * 256];   // W2^T hi: (n,k) at n*256+k
__device__ __align__(16) __nv_bfloat16 g_w2l[3 * 128 * 256];

// ---------------- CSR build ----------------
__global__ void k_zero_cnt() {
    int i = blockIdx.x * blockDim.x + threadIdx.x;
    if (i < NN) g_cnt[i] = 0;
}

__global__ void k_hist(const int* __restrict__ dst) {
    int i = blockIdx.x * blockDim.x + threadIdx.x;
    if (i < NE) atomicAdd(&g_cnt[dst[i]], 1);
}

__global__ __launch_bounds__(1024) void k_scan() {
    __shared__ int wsum[32];
    const int CH = 30;
    int tid = threadIdx.x;
    int base = tid * CH;
    int loc[CH];
    int s = 0;
#pragma unroll
    for (int i = 0; i < CH; i++) {
        int idx = base + i;
        loc[i] = (idx < NN) ? g_cnt[idx] : 0;
        s += loc[i];
    }
    int lane = tid & 31, wid = tid >> 5;
    int v = s;
#pragma unroll
    for (int off = 1; off < 32; off <<= 1) {
        int t = __shfl_up_sync(0xffffffffu, v, off);
        if (lane >= off) v += t;
    }
    if (lane == 31) wsum[wid] = v;
    __syncthreads();
    if (wid == 0) {
        int wv = wsum[lane];
#pragma unroll
        for (int off = 1; off < 32; off <<= 1) {
            int t = __shfl_up_sync(0xffffffffu, wv, off);
            if (lane >= off) wv += t;
        }
        wsum[lane] = wv;
    }
    __syncthreads();
    int run = v - s + (wid ? wsum[wid - 1] : 0);
#pragma unroll
    for (int i = 0; i < CH; i++) {
        int idx = base + i;
        if (idx < NN) {
            g_rowptr[idx] = run;
            run += loc[i];
            g_cnt[idx] = 0;
        }
    }
    if (tid == 1023) g_rowptr[NN] = run;
}

// ---------------- fused edge encoder + scatter ----------------
__global__ __launch_bounds__(256) void k_encscatter(
    const float* __restrict__ edge_attr, const int* __restrict__ src,
    const int* __restrict__ dst,
    const float* __restrict__ W, const float* __restrict__ bias)
{
    __shared__ ull sA2[128][17];
    __shared__ __align__(16) float sW[F_EDGE][HID];
    __shared__ int sPos[128];
    int p0 = blockIdx.x * 128;
    int tid = threadIdx.x;
    for (int i = tid; i < F_EDGE * HID; i += 256) ((float*)sW)[i] = W[i];
    if (tid < 128) {
        int e = p0 + tid;
        int d = dst[e];
        int rank = atomicAdd(&g_cnt[d], 1);
        int pos = g_rowptr[d] + rank;
        sPos[tid] = pos;
        g_srcs[pos] = src[e];
    }
    __syncthreads();
#pragma unroll
    for (int i = 0; i < 8; i++) {
        int idx = tid + i * 256;
        int r = idx >> 4, k = idx & 15;
        float v = edge_attr[(size_t)(p0 + r) * F_EDGE + k];
        sA2[r][k] = pack2(v, v);
    }
    __syncthreads();
    int tx = tid & 31, ty = tid >> 5;
    float2 b0 = *(const float2*)&bias[2 * tx];
    float2 b1 = *(const float2*)&bias[2 * tx + 64];
    ull ib0 = pack2(b0.x, b0.y), ib1 = pack2(b1.x, b1.y);
    ull acc[16][2];
#pragma unroll
    for (int i = 0; i < 16; i++) { acc[i][0] = ib0; acc[i][1] = ib1; }
#pragma unroll
    for (int k = 0; k < F_EDGE; k++) {
        ull w0 = *(const ull*)&sW[k][2 * tx];
        ull w1 = *(const ull*)&sW[k][2 * tx + 64];
#pragma unroll
        for (int i = 0; i < 16; i++) {
            ull a = sA2[ty * 16 + i][k];
            fma2(acc[i][0], a, w0);
            fma2(acc[i][1], a, w1);
        }
    }
#pragma unroll
    for (int i = 0; i < 16; i++) {
        size_t p = sPos[ty * 16 + i];
        float2 v0 = unpack2(acc[i][0]);
        float2 v1 = unpack2(acc[i][1]);
        *(__half2*)&g_eah[p * HID + 2 * tx]      = __float22half2_rn(v0);
        *(__half2*)&g_eah[p * HID + 2 * tx + 64] = __float22half2_rn(v1);
    }
}

// ---------------- weight conversion: W1^T, W2^T -> bf16 hi/lo planes ----------------
__global__ __launch_bounds__(256) void k_wconv(const float* __restrict__ w1,
                                               const float* __restrict__ w2)
{
    int i = blockIdx.x * 256 + threadIdx.x;
    if (i < 3 * 256 * 128) {
        int l = i >> 15, rem = i & 32767;
        int n = rem >> 7, k = rem & 127;
        float v = w1[l * 32768 + k * 256 + n];
        __nv_bfloat16 hi = __float2bfloat16(v);
        g_w1h[i] = hi;
        g_w1l[i] = __float2bfloat16(v - __bfloat162float(hi));

        int n2 = rem >> 8, k2 = rem & 255;
        float v2 = w2[l * 32768 + k2 * 128 + n2];
        __nv_bfloat16 hi2 = __float2bfloat16(v2);
        g_w2h[i] = hi2;
        g_w2l[i] = __float2bfloat16(v2 - __bfloat162float(hi2));
    }
}

// ---------------- node encoder ----------------
__global__ __launch_bounds__(256) void k_node_enc(
    const float* __restrict__ x, const float* __restrict__ W, const float* __restrict__ bias)
{
    __shared__ __align__(16) float sW[F_IN * HID];
    __shared__ __align__(16) float sB[HID];
    for (int i = threadIdx.x; i < F_IN * HID; i += 256) sW[i] = W[i];
    if (threadIdx.x < HID) sB[threadIdx.x] = bias[threadIdx.x];
    __syncthreads();
    int lane = threadIdx.x & 31;
    int warp = (blockIdx.x * 256 + threadIdx.x) >> 5;
    int nw = gridDim.x * 8;
    float4 bv = ((float4*)sB)[lane];
    for (int n = warp; n < NN; n += nw) {
        float a0 = x[n * F_IN + lane];
        float a1 = x[n * F_IN + 32 + lane];
        float4 acc = bv;
#pragma unroll
        for (int k = 0; k < F_IN; k++) {
            float ak = __shfl_sync(0xffffffffu, (k < 32) ? a0 : a1, k & 31);
            float4 w = ((const float4*)(sW + k * HID))[lane];
            acc.x = fmaf(ak, w.x, acc.x);
            acc.y = fmaf(ak, w.y, acc.y);
            acc.z = fmaf(ak, w.z, acc.z);
            acc.w = fmaf(ak, w.w, acc.w);
        }
        ((float4*)g_h)[n * 32 + lane] = acc;
        __half2 h0 = __float22half2_rn(make_float2(acc.x, acc.y));
        __half2 h1 = __float22half2_rn(make_float2(acc.z, acc.w));
        *(__half2*)&g_ninh[(size_t)n * HID + 4 * lane]     = h0;
        *(__half2*)&g_ninh[(size_t)n * HID + 4 * lane + 2] = h1;
    }
}

// ---------------- edge aggregation ----------------
__device__ __forceinline__ float4 load_h16(const __half* base, size_t row, int lane) {
    uint2 raw = *(const uint2*)(base + row * HID + lane * 4);
    float2 fa = __half22float2(*(__half2*)&raw.x);
    float2 fb = __half22float2(*(__half2*)&raw.y);
    return make_float4(fa.x, fa.y, fb.x, fb.y);
}

__global__ __launch_bounds__(256) void k_edge_agg(int layer, const float* __restrict__ t_arr)
{
    int lane = threadIdx.x & 31;
    int n = (blockIdx.x * 256 + threadIdx.x) >> 5;
    if (n >= NN) return;
    float tv = t_arr[layer];
    int p = g_rowptr[n], end = g_rowptr[n + 1];
    float4 sa = make_float4(0.f, 0.f, 0.f, 0.f), wa = sa;
    float4 sb = sa, wb = sa;
    for (; p + 4 <= end; p += 4) {
        int s0 = g_srcs[p], s1 = g_srcs[p + 1], s2 = g_srcs[p + 2], s3 = g_srcs[p + 3];
        float4 e0 = load_h16(g_eah, p, lane);
        float4 e1 = load_h16(g_eah, p + 1, lane);
        float4 e2 = load_h16(g_eah, p + 2, lane);
        float4 e3 = load_h16(g_eah, p + 3, lane);
        float4 h0 = load_h16(g_ninh, s0, lane);
        float4 h1 = load_h16(g_ninh, s1, lane);
        float4 h2 = load_h16(g_ninh, s2, lane);
        float4 h3 = load_h16(g_ninh, s3, lane);
#define DO_EDGE(hh, ee, S, W) { \
        float m0 = fmaxf(hh.x + ee.x, 0.f) + 1e-7f; \
        float m1 = fmaxf(hh.y + ee.y, 0.f) + 1e-7f; \
        float m2 = fmaxf(hh.z + ee.z, 0.f) + 1e-7f; \
        float m3 = fmaxf(hh.w + ee.w, 0.f) + 1e-7f; \
        float x0 = __expf(m0 * tv), x1 = __expf(m1 * tv); \
        float x2 = __expf(m2 * tv), x3 = __expf(m3 * tv); \
        S.x += x0; S.y += x1; S.z += x2; S.w += x3; \
        W.x = fmaf(m0, x0, W.x); W.y = fmaf(m1, x1, W.y); \
        W.z = fmaf(m2, x2, W.z); W.w = fmaf(m3, x3, W.w); }
        DO_EDGE(h0, e0, sa, wa);
        DO_EDGE(h1, e1, sb, wb);
        DO_EDGE(h2, e2, sa, wa);
        DO_EDGE(h3, e3, sb, wb);
    }
    for (; p < end; p++) {
        int s0 = g_srcs[p];
        float4 e0 = load_h16(g_eah, p, lane);
        float4 h0 = load_h16(g_ninh, s0, lane);
        DO_EDGE(h0, e0, sa, wa);
    }
#undef DO_EDGE
    sa.x += sb.x; sa.y += sb.y; sa.z += sb.z; sa.w += sb.w;
    wa.x += wb.x; wa.y += wb.y; wa.z += wb.z; wa.w += wb.w;
    float4 xr = load_h16(g_ninh, n, lane);   // additive term: fp16 table (h for l=0, prenorm else)
    float z[4];
    z[0] = wa.x / (sa.x + 1e-16f) + xr.x;
    z[1] = wa.y / (sa.y + 1e-16f) + xr.y;
    z[2] = wa.z / (sa.z + 1e-16f) + xr.z;
    z[3] = wa.w / (sa.w + 1e-16f) + xr.w;
    ushort hh[4], ll[4];
#pragma unroll
    for (int i = 0; i < 4; i++) {
        __nv_bfloat16 hi = __float2bfloat16(z[i]);
        __nv_bfloat16 lo = __float2bfloat16(z[i] - __bfloat162float(hi));
        hh[i] = __bfloat16_as_ushort(hi);
        ll[i] = __bfloat16_as_ushort(lo);
    }
    uint2 ph, pl;
    ph.x = (uint32_t)hh[0] | ((uint32_t)hh[1] << 16);
    ph.y = (uint32_t)hh[2] | ((uint32_t)hh[3] << 16);
    pl.x = (uint32_t)ll[0] | ((uint32_t)ll[1] << 16);
    pl.y = (uint32_t)ll[2] | ((uint32_t)ll[3] << 16);
    *(uint2*)&g_zh[(size_t)n * HID + 4 * lane] = ph;
    *(uint2*)&g_zl[(size_t)n * HID + 4 * lane] = pl;
}

// ---------------- fused MLP (wmma): h = (relu(LN(z@W1+b1)))@W2 + b2 (+res); mid stays in smem ----------------
// dyn smem phases (byte offsets):
//   P1: sAh[64][136] @0 (17408), sAl @17408 (17408)
//   P2: sC1[64][264] f32 @0 (67584)                      [sA dead]
//   P3: sMh[64][264] bf16 @67584 (33792), sMl @101376 (33792)   [reads sC1]
//   P4: GEMM2 reads sMh/sMl
//   P5: sC2[64][136] f32 @0 (34816)                      [sC1 dead]
//   stats @135168 (512)
#define WM_SMEM (135168 + 512)
__global__ __launch_bounds__(256) void k_wmlp(
    int layer,
    const float* __restrict__ b1, const float* __restrict__ lg, const float* __restrict__ lb,
    const float* __restrict__ b2, const float* __restrict__ gn, const float* __restrict__ bn,
    int use_res, int write_pre)
{
    extern __shared__ char smem[];
    __nv_bfloat16* sAh = (__nv_bfloat16*)smem;
    __nv_bfloat16* sAl = (__nv_bfloat16*)(smem + 17408);
    float* sC1 = (float*)smem;
    __nv_bfloat16* sMh = (__nv_bfloat16*)(smem + 67584);
    __nv_bfloat16* sMl = (__nv_bfloat16*)(smem + 101376);
    float* sC2 = (float*)smem;
    float* sStat = (float*)(smem + 135168);
    __shared__ float sB1[256], sG1[256], sBt1[256];
    __shared__ float sB2[128], sG2[128], sBt2[128];
    int tid = threadIdx.x;
    int n0 = blockIdx.x * 64;
    if (tid < 256) { sB1[tid] = b1[tid]; sG1[tid] = lg[tid]; sBt1[tid] = lb[tid]; }
    if (tid < 128) { sB2[tid] = b2[tid]; sG2[tid] = gn[tid]; sBt2[tid] = bn[tid]; }
    // load z tile (hi/lo)
    for (int u = tid; u < 64 * 32; u += 256) {
        int r = u >> 5, c4 = u & 31;
        int n = n0 + r;
        uint2 vh = make_uint2(0u, 0u), vl = vh;
        if (n < NN) {
            vh = *(const uint2*)&g_zh[(size_t)n * HID + c4 * 4];
            vl = *(const uint2*)&g_zl[(size_t)n * HID + c4 * 4];
        }
        *(uint2*)&sAh[r * 136 + c4 * 4] = vh;
        *(uint2*)&sAl[r * 136 + c4 * 4] = vl;
    }
    __syncthreads();

    int w = tid >> 5;
    int wm = w >> 2, wn = w & 3;
    const __nv_bfloat16* w1h = g_w1h + layer * 32768;
    const __nv_bfloat16* w1l = g_w1l + layer * 32768;
    {
        // ---------- GEMM1: [64x128] @ [128x256] ----------
        wmma::fragment<wmma::accumulator, 16, 16, 16, float> c[2][4];
#pragma unroll
        for (int i = 0; i < 2; i++)
#pragma unroll
            for (int j = 0; j < 4; j++) wmma::fill_fragment(c[i][j], 0.f);
#pragma unroll
        for (int ks = 0; ks < 8; ks++) {
            wmma::fragment<wmma::matrix_a, 16, 16, 16, __nv_bfloat16, wmma::row_major> ah[2], al[2];
#pragma unroll
            for (int i = 0; i < 2; i++) {
                wmma::load_matrix_sync(ah[i], sAh + (wm * 32 + i * 16) * 136 + ks * 16, 136);
                wmma::load_matrix_sync(al[i], sAl + (wm * 32 + i * 16) * 136 + ks * 16, 136);
            }
#pragma unroll
            for (int j = 0; j < 4; j++) {
                int ncol = wn * 64 + j * 16;
                wmma::fragment<wmma::matrix_b, 16, 16, 16, __nv_bfloat16, wmma::col_major> bh, bl;
                wmma::load_matrix_sync(bh, w1h + ncol * 128 + ks * 16, 128);
                wmma::load_matrix_sync(bl, w1l + ncol * 128 + ks * 16, 128);
#pragma unroll
                for (int i = 0; i < 2; i++) {
                    wmma::mma_sync(c[i][j], ah[i], bh, c[i][j]);
                    wmma::mma_sync(c[i][j], al[i], bh, c[i][j]);
                    wmma::mma_sync(c[i][j], ah[i], bl, c[i][j]);
                }
            }
        }
        __syncthreads();   // sA dead; sC1 takes over bytes
#pragma unroll
        for (int i = 0; i < 2; i++)
#pragma unroll
            for (int j = 0; j < 4; j++)
                wmma::store_matrix_sync(sC1 + (wm * 32 + i * 16) * 264 + wn * 64 + j * 16,
                                        c[i][j], 264, wmma::mem_row_major);
    }
    __syncthreads();
    // ---------- LN1 stats ----------
    {
        int r = tid >> 2, q = tid & 3;
        float sum = 0.f, sq = 0.f;
#pragma unroll 8
        for (int c0 = 0; c0 < 64; c0++) {
            float v = sC1[r * 264 + q * 64 + c0] + sB1[q * 64 + c0];
            sum += v; sq = fmaf(v, v, sq);
        }
        sum += __shfl_xor_sync(0xffffffffu, sum, 1);
        sq  += __shfl_xor_sync(0xffffffffu, sq, 1);
        sum += __shfl_xor_sync(0xffffffffu, sum, 2);
        sq  += __shfl_xor_sync(0xffffffffu, sq, 2);
        if (q == 0) {
            float m = sum * (1.f / 256.f);
            sStat[r] = m;
            sStat[64 + r] = rsqrtf(sq * (1.f / 256.f) - m * m + 1e-5f);
        }
    }
    __syncthreads();
    // ---------- mid = relu(LN(..)) -> smem bf16 hi/lo ----------
    for (int u = tid; u < 64 * 64; u += 256) {
        int r = u >> 6, c4 = u & 63;
        float m = sStat[r], rstd = sStat[64 + r];
#pragma unroll
        for (int i = 0; i < 4; i++) {
            int cc = c4 * 4 + i;
            float v = sC1[r * 264 + cc] + sB1[cc];
            float o = fmaxf((v - m) * rstd * sG1[cc] + sBt1[cc], 0.f);
            __nv_bfloat16 hi = __float2bfloat16(o);
            sMh[r * 264 + cc] = hi;
            sMl[r * 264 + cc] = __float2bfloat16(o - __bfloat162float(hi));
        }
    }
    __syncthreads();
    const __nv_bfloat16* w2h = g_w2h + layer * 32768;
    const __nv_bfloat16* w2l = g_w2l + layer * 32768;
    {
        // ---------- GEMM2: [64x256] @ [256x128] ----------
        wmma::fragment<wmma::accumulator, 16, 16, 16, float> c2[2][2];
#pragma unroll
        for (int i = 0; i < 2; i++)
#pragma unroll
            for (int j = 0; j < 2; j++) wmma::fill_fragment(c2[i][j], 0.f);
#pragma unroll
        for (int ks = 0; ks < 16; ks++) {
            wmma::fragment<wmma::matrix_a, 16, 16, 16, __nv_bfloat16, wmma::row_major> ah[2], al[2];
#pragma unroll
            for (int i = 0; i < 2; i++) {
                wmma::load_matrix_sync(ah[i], sMh + (wm * 32 + i * 16) * 264 + ks * 16, 264);
                wmma::load_matrix_sync(al[i], sMl + (wm * 32 + i * 16) * 264 + ks * 16, 264);
            }
#pragma unroll
            for (int j = 0; j < 2; j++) {
                int ncol = wn * 32 + j * 16;
                wmma::fragment<wmma::matrix_b, 16, 16, 16, __nv_bfloat16, wmma::col_major> bh, bl;
                wmma::load_matrix_sync(bh, w2h + ncol * 256 + ks * 16, 256);
                wmma::load_matrix_sync(bl, w2l + ncol * 256 + ks * 16, 256);
#pragma unroll
                for (int i = 0; i < 2; i++) {
                    wmma::mma_sync(c2[i][j], ah[i], bh, c2[i][j]);
                    wmma::mma_sync(c2[i][j], al[i], bh, c2[i][j]);
                    wmma::mma_sync(c2[i][j], ah[i], bl, c2[i][j]);
                }
            }
        }
        // sC2 overlaps sC1 (dead since LN1/mid phase); all warps past sC1 reads after the
        // __syncthreads() preceding GEMM2, so storing here is safe.
#pragma unroll
        for (int i = 0; i < 2; i++)
#pragma unroll
            for (int j = 0; j < 2; j++)
                wmma::store_matrix_sync(sC2 + (wm * 32 + i * 16) * 136 + wn * 32 + j * 16,
                                        c2[i][j], 136, wmma::mem_row_major);
    }
    __syncthreads();
    // ---------- bias + residual ----------
    for (int u = tid; u < 64 * 32; u += 256) {
        int r = u >> 5, c4 = u & 31;
        int n = n0 + r;
        float4 res = make_float4(0.f, 0.f, 0.f, 0.f);
        if (use_res && n < NN) res = *(const float4*)&g_h[n * HID + c4 * 4];
#pragma unroll
        for (int i = 0; i < 4; i++) {
            int cc = c4 * 4 + i;
            sC2[r * 136 + cc] += sB2[cc] + ((const float*)&res)[i];
        }
    }
    __syncthreads();
    // ---------- LN2 stats (for prenorm) ----------
    {
        int r = tid >> 2, q = tid & 3;
        float sum = 0.f, sq = 0.f;
#pragma unroll 8
        for (int c0 = 0; c0 < 32; c0++) {
            float v = sC2[r * 136 + q * 32 + c0];
            sum += v; sq = fmaf(v, v, sq);
        }
        sum += __shfl_xor_sync(0xffffffffu, sum, 1);
        sq  += __shfl_xor_sync(0xffffffffu, sq, 1);
        sum += __shfl_xor_sync(0xffffffffu, sum, 2);
        sq  += __shfl_xor_sync(0xffffffffu, sq, 2);
        if (q == 0) {
            float m = sum * (1.f / 128.f);
            sStat[r] = m;
            sStat[64 + r] = rsqrtf(sq * (1.f / 128.f) - m * m + 1e-5f);
        }
    }
    __syncthreads();
    // ---------- write h (+ prenorm -> ninh) ----------
    for (int u = tid; u < 64 * 32; u += 256) {
        int r = u >> 5, c4 = u & 31;
        int n = n0 + r;
        if (n >= NN) continue;
        float4 v;
        v.x = sC2[r * 136 + c4 * 4 + 0];
        v.y = sC2[r * 136 + c4 * 4 + 1];
        v.z = sC2[r * 136 + c4 * 4 + 2];
        v.w = sC2[r * 136 + c4 * 4 + 3];
        *(float4*)&g_h[n * HID + c4 * 4] = v;
        if (write_pre) {
            float m = sStat[r], rstd = sStat[64 + r];
            float4 o;
            o.x = fmaxf((v.x - m) * rstd * sG2[c4 * 4 + 0] + sBt2[c4 * 4 + 0], 0.f);
            o.y = fmaxf((v.y - m) * rstd * sG2[c4 * 4 + 1] + sBt2[c4 * 4 + 1], 0.f);
            o.z = fmaxf((v.z - m) * rstd * sG2[c4 * 4 + 2] + sBt2[c4 * 4 + 2], 0.f);
            o.w = fmaxf((v.w - m) * rstd * sG2[c4 * 4 + 3] + sBt2[c4 * 4 + 3], 0.f);
            uint2 hp;
            __half2 ha = __float22half2_rn(make_float2(o.x, o.y));
            __half2 hb = __float22half2_rn(make_float2(o.z, o.w));
            hp.x = *(uint32_t*)&ha; hp.y = *(uint32_t*)&hb;
            *(uint2*)&g_ninh[(size_t)n * HID + c4 * 4] = hp;
        }
    }
}

// ---------------- classifier ----------------
__global__ __launch_bounds__(256) void k_classifier(
    const float* __restrict__ gmm, const float* __restrict__ bb,
    const float* __restrict__ lw, const float* __restrict__ lbias,
    float* __restrict__ out)
{
    int lane = threadIdx.x & 31;
    int n = (blockIdx.x * 256 + threadIdx.x) >> 5;
    if (n >= NN) return;
    float4 v = ((const float4*)g_h)[n * 32 + lane];
    float s = v.x + v.y + v.z + v.w;
    float q = v.x * v.x + v.y * v.y + v.z * v.z + v.w * v.w;
#pragma unroll
    for (int off = 16; off; off >>= 1) {
        s += __shfl_xor_sync(0xffffffffu, s, off);
        q += __shfl_xor_sync(0xffffffffu, q, off);
    }
    float m = s * (1.f / 128.f);
    float var = q * (1.f / 128.f) - m * m;
    float rstd = rsqrtf(var + 1e-5f);
    float4 g4 = ((const float4*)gmm)[lane];
    float4 b4 = ((const float4*)bb)[lane];
    float h0 = fmaxf((v.x - m) * rstd * g4.x + b4.x, 0.f);
    float h1 = fmaxf((v.y - m) * rstd * g4.y + b4.y, 0.f);
    float h2 = fmaxf((v.z - m) * rstd * g4.z + b4.z, 0.f);
    float h3 = fmaxf((v.w - m) * rstd * g4.w + b4.w, 0.f);
    int c0 = lane * 4;
    float r[NCLS];
#pragma unroll
    for (int j = 0; j < NCLS; j++) {
        float p = h0 * lw[c0 * NCLS + j];
        p = fmaf(h1, lw[(c0 + 1) * NCLS + j], p);
        p = fmaf(h2, lw[(c0 + 2) * NCLS + j], p);
        p = fmaf(h3, lw[(c0 + 3) * NCLS + j], p);
#pragma unroll
        for (int off = 16; off; off >>= 1) p += __shfl_xor_sync(0xffffffffu, p, off);
        r[j] = p;
    }
#pragma unroll
    for (int j = 0; j < NCLS; j++)
        if (lane == j) out[n * NCLS + j] = r[j] + lbias[j];
}

// ---------------- launch ----------------
extern "C" void kernel_launch(void* const* d_in, const int* in_sizes, int n_in,
                              void* d_out, int out_size)
{
    const float* x         = (const float*)d_in[0];
    const float* edge_attr = (const float*)d_in[1];
    const float* node_w    = (const float*)d_in[2];
    const float* node_b    = (const float*)d_in[3];
    const float* edge_w    = (const float*)d_in[4];
    const float* edge_b    = (const float*)d_in[5];
    const float* mlp1_w    = (const float*)d_in[6];
    const float* mlp1_b    = (const float*)d_in[7];
    const float* ln_g      = (const float*)d_in[8];
    const float* ln_b      = (const float*)d_in[9];
    const float* mlp2_w    = (const float*)d_in[10];
    const float* mlp2_b    = (const float*)d_in[11];
    const float* t         = (const float*)d_in[12];
    const float* norm_g    = (const float*)d_in[13];
    const float* norm_b    = (const float*)d_in[14];
    const float* lin_w     = (const float*)d_in[15];
    const float* lin_b     = (const float*)d_in[16];
    const int*   edge_index= (const int*)d_in[17];
    const int* src = edge_index;
    const int* dst = edge_index + NE;
    float* out = (float*)d_out;

    static int attr_done = 0;
    if (!attr_done) {
        cudaFuncSetAttribute(k_wmlp, cudaFuncAttributeMaxDynamicSharedMemorySize, WM_SMEM);
        attr_done = 1;
    }

    // g_cnt is zero on entry (module-load zero; trailing k_zero_cnt each replay)
    k_node_enc<<<1184, 256>>>(x, node_w, node_b);                          // 0
    k_hist<<<(NE + 255) / 256, 256>>>(dst);                                // 1
    k_scan<<<1, 1024>>>();                                                 // 2
    k_encscatter<<<NE / 128, 256>>>(edge_attr, src, dst, edge_w, edge_b);  // 3 <- profiled
    k_wconv<<<384, 256>>>(mlp1_w, mlp2_w);                                 // 4

    const int GGRID = (NN + 63) / 64;   // 469
    for (int l = 0; l < 3; l++) {
        k_edge_agg<<<(NN * 32 + 255) / 256, 256>>>(l, t);
        k_wmlp<<<GGRID, 256, WM_SMEM>>>(l,
                                        mlp1_b + l * 256, ln_g + l * 256, ln_b + l * 256,
                                        mlp2_b + l * HID,
                                        norm_g + (l + 1) * HID, norm_b + (l + 1) * HID,
                                        l > 0, l < 2 ? 1 : 0);
    }
    k_classifier<<<(NN * 32 + 255) / 256, 256>>>(norm_g, norm_b, lin_w, lin_b, out);
    k_zero_cnt<<<(NN + 255) / 256, 256>>>();
}

// round 13
// speedup vs baseline: 1.0006x; 1.0006x over previous
#include <cuda_runtime.h>
#include <cuda_fp16.h>
#include <cuda_bf16.h>
#include <mma.h>
#include <cstdint>

using namespace nvcuda;

#define NN 30000
#define NE 480000
#define HID 128
#define F_IN 64
#define F_EDGE 16
#define NCLS 10

typedef unsigned long long ull;

__device__ __forceinline__ ull pack2(float lo, float hi) {
    ull r; asm("mov.b64 %0, {%1, %2};" : "=l"(r) : "f"(lo), "f"(hi)); return r;
}
__device__ __forceinline__ float2 unpack2(ull v) {
    float2 r; asm("mov.b64 {%0, %1}, %2;" : "=f"(r.x), "=f"(r.y) : "l"(v)); return r;
}
__device__ __forceinline__ void fma2(ull& d, ull a, ull b) {
    asm("fma.rn.f32x2 %0, %1, %2, %0;" : "+l"(d) : "l"(a), "l"(b));
}
__device__ __forceinline__ float ex2(float x) {
    float r; asm("ex2.approx.f32 %0, %1;" : "=f"(r) : "f"(x)); return r;
}

// ---------------- device scratch ----------------
__device__ __align__(16) __half g_eah[(size_t)NE * HID];
__device__ int   g_srcs[NE];
__device__ int   g_rowptr[NN + 1];
__device__ int   g_cnt[NN];
__device__ __align__(16) float  g_h[NN * HID];
__device__ __align__(16) float  g_nin[NN * HID];
__device__ __align__(16) __half g_ninh[NN * HID];
__device__ __align__(16) __nv_bfloat16 g_zh[NN * HID];
__device__ __align__(16) __nv_bfloat16 g_zl[NN * HID];
__device__ __align__(16) __nv_bfloat16 g_midh[(size_t)NN * 256];
__device__ __align__(16) __nv_bfloat16 g_midl[(size_t)NN * 256];
__device__ __align__(16) __nv_bfloat16 g_w1h[3 * 256 * 128];   // W1^T hi: (n,k) at n*128+k
__device__ __align__(16) __nv_bfloat16 g_w1l[3 * 256 * 128];
__device__ __align__(16) __nv_bfloat16 g_w2h[3 * 128 * 256];   // W2^T hi: (n,k) at n*256+k
__device__ __align__(16) __nv_bfloat16 g_w2l[3 * 128 * 256];

// ---------------- CSR build ----------------
__global__ void k_zero_cnt() {
    int i = blockIdx.x * blockDim.x + threadIdx.x;
    if (i < NN) g_cnt[i] = 0;
}

__global__ void k_hist(const int* __restrict__ dst) {
    int i = blockIdx.x * blockDim.x + threadIdx.x;
    if (i < NE) atomicAdd(&g_cnt[dst[i]], 1);
}

__global__ __launch_bounds__(1024) void k_scan() {
    __shared__ int wsum[32];
    const int CH = 30;
    int tid = threadIdx.x;
    int base = tid * CH;
    int loc[CH];
    int s = 0;
#pragma unroll
    for (int i = 0; i < CH; i++) {
        int idx = base + i;
        loc[i] = (idx < NN) ? g_cnt[idx] : 0;
        s += loc[i];
    }
    int lane = tid & 31, wid = tid >> 5;
    int v = s;
#pragma unroll
    for (int off = 1; off < 32; off <<= 1) {
        int t = __shfl_up_sync(0xffffffffu, v, off);
        if (lane >= off) v += t;
    }
    if (lane == 31) wsum[wid] = v;
    __syncthreads();
    if (wid == 0) {
        int wv = wsum[lane];
#pragma unroll
        for (int off = 1; off < 32; off <<= 1) {
            int t = __shfl_up_sync(0xffffffffu, wv, off);
            if (lane >= off) wv += t;
        }
        wsum[lane] = wv;
    }
    __syncthreads();
    int run = v - s + (wid ? wsum[wid - 1] : 0);
#pragma unroll
    for (int i = 0; i < CH; i++) {
        int idx = base + i;
        if (idx < NN) {
            g_rowptr[idx] = run;
            run += loc[i];
            g_cnt[idx] = 0;
        }
    }
    if (tid == 1023) g_rowptr[NN] = run;
}

// ---------------- fused edge encoder + scatter: 64 edges/block (low regs, high occ) ----------------
__global__ __launch_bounds__(256) void k_encscatter(
    const float* __restrict__ edge_attr, const int* __restrict__ src,
    const int* __restrict__ dst,
    const float* __restrict__ W, const float* __restrict__ bias)
{
    __shared__ ull sA2[64][17];
    __shared__ __align__(16) float sW[F_EDGE][HID];
    __shared__ int sPos[64];
    int p0 = blockIdx.x * 64;
    int tid = threadIdx.x;
    for (int i = tid; i < F_EDGE * HID; i += 256) ((float*)sW)[i] = W[i];
    if (tid < 64) {
        int e = p0 + tid;
        int d = dst[e];
        int rank = atomicAdd(&g_cnt[d], 1);
        int pos = g_rowptr[d] + rank;
        sPos[tid] = pos;
        g_srcs[pos] = src[e];
    }
    __syncthreads();
#pragma unroll
    for (int i = 0; i < 4; i++) {
        int idx = tid + i * 256;
        int r = idx >> 4, k = idx & 15;
        float v = edge_attr[(size_t)(p0 + r) * F_EDGE + k];
        sA2[r][k] = pack2(v, v);
    }
    __syncthreads();
    int tx = tid & 31, ty = tid >> 5;
    float2 b0 = *(const float2*)&bias[2 * tx];
    float2 b1 = *(const float2*)&bias[2 * tx + 64];
    ull ib0 = pack2(b0.x, b0.y), ib1 = pack2(b1.x, b1.y);
    ull acc[8][2];
#pragma unroll
    for (int i = 0; i < 8; i++) { acc[i][0] = ib0; acc[i][1] = ib1; }
#pragma unroll
    for (int k = 0; k < F_EDGE; k++) {
        ull w0 = *(const ull*)&sW[k][2 * tx];
        ull w1 = *(const ull*)&sW[k][2 * tx + 64];
#pragma unroll
        for (int i = 0; i < 8; i++) {
            ull a = sA2[ty * 8 + i][k];
            fma2(acc[i][0], a, w0);
            fma2(acc[i][1], a, w1);
        }
    }
#pragma unroll
    for (int i = 0; i < 8; i++) {
        size_t p = sPos[ty * 8 + i];
        float2 v0 = unpack2(acc[i][0]);
        float2 v1 = unpack2(acc[i][1]);
        *(__half2*)&g_eah[p * HID + 2 * tx]      = __float22half2_rn(v0);
        *(__half2*)&g_eah[p * HID + 2 * tx + 64] = __float22half2_rn(v1);
    }
}

// ---------------- weight conversion: W1^T, W2^T -> bf16 hi/lo planes ----------------
__global__ __launch_bounds__(256) void k_wconv(const float* __restrict__ w1,
                                               const float* __restrict__ w2)
{
    int i = blockIdx.x * 256 + threadIdx.x;
    if (i < 3 * 256 * 128) {
        int l = i >> 15, rem = i & 32767;
        int n = rem >> 7, k = rem & 127;
        float v = w1[l * 32768 + k * 256 + n];
        __nv_bfloat16 hi = __float2bfloat16(v);
        g_w1h[i] = hi;
        g_w1l[i] = __float2bfloat16(v - __bfloat162float(hi));

        int n2 = rem >> 8, k2 = rem & 255;
        float v2 = w2[l * 32768 + k2 * 128 + n2];
        __nv_bfloat16 hi2 = __float2bfloat16(v2);
        g_w2h[i] = hi2;
        g_w2l[i] = __float2bfloat16(v2 - __bfloat162float(hi2));
    }
}

// ---------------- node encoder ----------------
__global__ __launch_bounds__(256) void k_node_enc(
    const float* __restrict__ x, const float* __restrict__ W, const float* __restrict__ bias)
{
    __shared__ __align__(16) float sW[F_IN * HID];
    __shared__ __align__(16) float sB[HID];
    for (int i = threadIdx.x; i < F_IN * HID; i += 256) sW[i] = W[i];
    if (threadIdx.x < HID) sB[threadIdx.x] = bias[threadIdx.x];
    __syncthreads();
    int lane = threadIdx.x & 31;
    int warp = (blockIdx.x * 256 + threadIdx.x) >> 5;
    int nw = gridDim.x * 8;
    float4 bv = ((float4*)sB)[lane];
    for (int n = warp; n < NN; n += nw) {
        float a0 = x[n * F_IN + lane];
        float a1 = x[n * F_IN + 32 + lane];
        float4 acc = bv;
#pragma unroll
        for (int k = 0; k < F_IN; k++) {
            float ak = __shfl_sync(0xffffffffu, (k < 32) ? a0 : a1, k & 31);
            float4 w = ((const float4*)(sW + k * HID))[lane];
            acc.x = fmaf(ak, w.x, acc.x);
            acc.y = fmaf(ak, w.y, acc.y);
            acc.z = fmaf(ak, w.z, acc.z);
            acc.w = fmaf(ak, w.w, acc.w);
        }
        ((float4*)g_h)[n * 32 + lane] = acc;
        __half2 h0 = __float22half2_rn(make_float2(acc.x, acc.y));
        __half2 h1 = __float22half2_rn(make_float2(acc.z, acc.w));
        *(__half2*)&g_ninh[(size_t)n * HID + 4 * lane]     = h0;
        *(__half2*)&g_ninh[(size_t)n * HID + 4 * lane + 2] = h1;
    }
}

// ---------------- edge aggregation: half2 math + ex2 ----------------
__global__ __launch_bounds__(256) void k_edge_agg(int layer, const float* __restrict__ t_arr)
{
    int lane = threadIdx.x & 31;
    int n = (blockIdx.x * 256 + threadIdx.x) >> 5;
    if (n >= NN) return;
    const float4* x4 = (const float4*)((layer == 0) ? g_h : g_nin);
    float tl = t_arr[layer] * 1.44269504f;   // t * log2(e)
    int p = g_rowptr[n], end = g_rowptr[n + 1];
    const uint2* ea2 = (const uint2*)g_eah;   // 32 uint2 per row
    const uint2* nn2 = (const uint2*)g_ninh;
    float4 sa = make_float4(0.f, 0.f, 0.f, 0.f), wa = sa;
    float4 sb = sa, wb = sa;
    const __half2 z2 = __float2half2_rn(0.f);
#define DO_EDGE(eraw, hraw, S, W) { \
    __half2 _m0 = __hmax2(__hadd2(*(__half2*)&(hraw).x, *(__half2*)&(eraw).x), z2); \
    __half2 _m1 = __hmax2(__hadd2(*(__half2*)&(hraw).y, *(__half2*)&(eraw).y), z2); \
    float2 _f0 = __half22float2(_m0); \
    float2 _f1 = __half22float2(_m1); \
    float _x0 = ex2(_f0.x * tl), _x1 = ex2(_f0.y * tl); \
    float _x2 = ex2(_f1.x * tl), _x3 = ex2(_f1.y * tl); \
    S.x += _x0; S.y += _x1; S.z += _x2; S.w += _x3; \
    W.x = fmaf(_f0.x, _x0, W.x); W.y = fmaf(_f0.y, _x1, W.y); \
    W.z = fmaf(_f1.x, _x2, W.z); W.w = fmaf(_f1.y, _x3, W.w); }
    for (; p + 4 <= end; p += 4) {
        int s0 = g_srcs[p], s1 = g_srcs[p + 1], s2 = g_srcs[p + 2], s3 = g_srcs[p + 3];
        uint2 e0 = ea2[(size_t)p * 32 + lane];
        uint2 e1 = ea2[(size_t)(p + 1) * 32 + lane];
        uint2 e2 = ea2[(size_t)(p + 2) * 32 + lane];
        uint2 e3 = ea2[(size_t)(p + 3) * 32 + lane];
        uint2 h0 = nn2[(size_t)s0 * 32 + lane];
        uint2 h1 = nn2[(size_t)s1 * 32 + lane];
        uint2 h2 = nn2[(size_t)s2 * 32 + lane];
        uint2 h3 = nn2[(size_t)s3 * 32 + lane];
        DO_EDGE(e0, h0, sa, wa);
        DO_EDGE(e1, h1, sb, wb);
        DO_EDGE(e2, h2, sa, wa);
        DO_EDGE(e3, h3, sb, wb);
    }
    for (; p < end; p++) {
        int s0 = g_srcs[p];
        uint2 e0 = ea2[(size_t)p * 32 + lane];
        uint2 h0 = nn2[(size_t)s0 * 32 + lane];
        DO_EDGE(e0, h0, sa, wa);
    }
#undef DO_EDGE
    sa.x += sb.x; sa.y += sb.y; sa.z += sb.z; sa.w += sb.w;
    wa.x += wb.x; wa.y += wb.y; wa.z += wb.z; wa.w += wb.w;
    float4 xr = x4[n * 32 + lane];
    float z[4];
    z[0] = wa.x / (sa.x + 1e-16f) + xr.x;
    z[1] = wa.y / (sa.y + 1e-16f) + xr.y;
    z[2] = wa.z / (sa.z + 1e-16f) + xr.z;
    z[3] = wa.w / (sa.w + 1e-16f) + xr.w;
    ushort hh[4], ll[4];
#pragma unroll
    for (int i = 0; i < 4; i++) {
        __nv_bfloat16 hi = __float2bfloat16(z[i]);
        __nv_bfloat16 lo = __float2bfloat16(z[i] - __bfloat162float(hi));
        hh[i] = __bfloat16_as_ushort(hi);
        ll[i] = __bfloat16_as_ushort(lo);
    }
    uint2 ph, pl;
    ph.x = (uint32_t)hh[0] | ((uint32_t)hh[1] << 16);
    ph.y = (uint32_t)hh[2] | ((uint32_t)hh[3] << 16);
    pl.x = (uint32_t)ll[0] | ((uint32_t)ll[1] << 16);
    pl.y = (uint32_t)ll[2] | ((uint32_t)ll[3] << 16);
    *(uint2*)&g_zh[(size_t)n * HID + 4 * lane] = ph;
    *(uint2*)&g_zl[(size_t)n * HID + 4 * lane] = pl;
}

// ---------------- GEMM1 (wmma): mid = relu(LN(z @ W1 + b1)), tile 64x256, smem union ----------------
#define G1_SMEM (67584 + 512)
__global__ __launch_bounds__(256) void k_wgemm1(
    int layer, const float* __restrict__ b1,
    const float* __restrict__ lg, const float* __restrict__ lb)
{
    extern __shared__ char smem[];
    __nv_bfloat16* sAh = (__nv_bfloat16*)smem;
    __nv_bfloat16* sAl = (__nv_bfloat16*)(smem + 17408);
    float* sC = (float*)smem;                       // UNION with sAh/sAl
    float* sStat = (float*)(smem + 67584);
    __shared__ float sB[256], sG[256], sBt[256];
    int tid = threadIdx.x;
    int n0 = blockIdx.x * 64;
    if (tid < 256) { sB[tid] = b1[tid]; sG[tid] = lg[tid]; sBt[tid] = lb[tid]; }
    for (int u = tid; u < 64 * 32; u += 256) {
        int r = u >> 5, c4 = u & 31;
        int n = n0 + r;
        uint2 vh = make_uint2(0u, 0u), vl = vh;
        if (n < NN) {
            vh = *(const uint2*)&g_zh[(size_t)n * HID + c4 * 4];
            vl = *(const uint2*)&g_zl[(size_t)n * HID + c4 * 4];
        }
        *(uint2*)&sAh[r * 136 + c4 * 4] = vh;
        *(uint2*)&sAl[r * 136 + c4 * 4] = vl;
    }
    __syncthreads();

    int w = tid >> 5;
    int wm = w >> 2, wn = w & 3;
    wmma::fragment<wmma::accumulator, 16, 16, 16, float> c[2][4];
#pragma unroll
    for (int i = 0; i < 2; i++)
#pragma unroll
        for (int j = 0; j < 4; j++) wmma::fill_fragment(c[i][j], 0.f);
    const __nv_bfloat16* w1h = g_w1h + layer * 32768;
    const __nv_bfloat16* w1l = g_w1l + layer * 32768;
#pragma unroll
    for (int ks = 0; ks < 8; ks++) {
        wmma::fragment<wmma::matrix_a, 16, 16, 16, __nv_bfloat16, wmma::row_major> ah[2], al[2];
#pragma unroll
        for (int i = 0; i < 2; i++) {
            wmma::load_matrix_sync(ah[i], sAh + (wm * 32 + i * 16) * 136 + ks * 16, 136);
            wmma::load_matrix_sync(al[i], sAl + (wm * 32 + i * 16) * 136 + ks * 16, 136);
        }
#pragma unroll
        for (int j = 0; j < 4; j++) {
            int ncol = wn * 64 + j * 16;
            wmma::fragment<wmma::matrix_b, 16, 16, 16, __nv_bfloat16, wmma::col_major> bh, bl;
            wmma::load_matrix_sync(bh, w1h + ncol * 128 + ks * 16, 128);
            wmma::load_matrix_sync(bl, w1l + ncol * 128 + ks * 16, 128);
#pragma unroll
            for (int i = 0; i < 2; i++) {
                wmma::mma_sync(c[i][j], ah[i], bh, c[i][j]);
                wmma::mma_sync(c[i][j], al[i], bh, c[i][j]);
                wmma::mma_sync(c[i][j], ah[i], bl, c[i][j]);
            }
        }
    }
    __syncthreads();   // all warps done reading sA before sC overwrites it
#pragma unroll
    for (int i = 0; i < 2; i++)
#pragma unroll
        for (int j = 0; j < 4; j++)
            wmma::store_matrix_sync(sC + (wm * 32 + i * 16) * 264 + wn * 64 + j * 16,
                                    c[i][j], 264, wmma::mem_row_major);
    __syncthreads();
    {
        int r = tid >> 2, q = tid & 3;
        float sum = 0.f, sq = 0.f;
#pragma unroll 8
        for (int c0 = 0; c0 < 64; c0++) {
            float v = sC[r * 264 + q * 64 + c0] + sB[q * 64 + c0];
            sum += v; sq = fmaf(v, v, sq);
        }
        sum += __shfl_xor_sync(0xffffffffu, sum, 1);
        sq  += __shfl_xor_sync(0xffffffffu, sq, 1);
        sum += __shfl_xor_sync(0xffffffffu, sum, 2);
        sq  += __shfl_xor_sync(0xffffffffu, sq, 2);
        if (q == 0) {
            float m = sum * (1.f / 256.f);
            sStat[r] = m;
            sStat[64 + r] = rsqrtf(sq * (1.f / 256.f) - m * m + 1e-5f);
        }
    }
    __syncthreads();
    for (int u = tid; u < 64 * 64; u += 256) {
        int r = u >> 6, c4 = u & 63;
        int n = n0 + r;
        if (n >= NN) continue;
        float m = sStat[r], rstd = sStat[64 + r];
        ushort hh[4], ll[4];
#pragma unroll
        for (int i = 0; i < 4; i++) {
            int cc = c4 * 4 + i;
            float v = sC[r * 264 + cc] + sB[cc];
            float o = fmaxf((v - m) * rstd * sG[cc] + sBt[cc], 0.f);
            __nv_bfloat16 hi = __float2bfloat16(o);
            __nv_bfloat16 lo = __float2bfloat16(o - __bfloat162float(hi));
            hh[i] = __bfloat16_as_ushort(hi);
            ll[i] = __bfloat16_as_ushort(lo);
        }
        uint2 vh, vl;
        vh.x = (uint32_t)hh[0] | ((uint32_t)hh[1] << 16);
        vh.y = (uint32_t)hh[2] | ((uint32_t)hh[3] << 16);
        vl.x = (uint32_t)ll[0] | ((uint32_t)ll[1] << 16);
        vl.y = (uint32_t)ll[2] | ((uint32_t)ll[3] << 16);
        *(uint2*)&g_midh[(size_t)n * 256 + c4 * 4] = vh;
        *(uint2*)&g_midl[(size_t)n * 256 + c4 * 4] = vl;
    }
}

// ---------------- GEMM2 (wmma): h = mid @ W2 + b2 (+res); fused prenorm. tile 64x128, smem union ----------------
#define G2_SMEM (67584 + 512)
__global__ __launch_bounds__(256) void k_wgemm2(
    int layer, const float* __restrict__ b2,
    const float* __restrict__ gn, const float* __restrict__ bn,
    int use_res, int write_pre)
{
    extern __shared__ char smem[];
    __nv_bfloat16* sAh = (__nv_bfloat16*)smem;
    __nv_bfloat16* sAl = (__nv_bfloat16*)(smem + 33792);
    float* sC = (float*)smem;                       // UNION with sAh
    float* sStat = (float*)(smem + 67584);
    __shared__ float sB[128], sG[128], sBt[128];
    int tid = threadIdx.x;
    int n0 = blockIdx.x * 64;
    if (tid < 128) { sB[tid] = b2[tid]; sG[tid] = gn[tid]; sBt[tid] = bn[tid]; }
    for (int u = tid; u < 64 * 64; u += 256) {
        int r = u >> 6, c4 = u & 63;
        int n = n0 + r;
        uint2 vh = make_uint2(0u, 0u), vl = vh;
        if (n < NN) {
            vh = *(const uint2*)&g_midh[(size_t)n * 256 + c4 * 4];
            vl = *(const uint2*)&g_midl[(size_t)n * 256 + c4 * 4];
        }
        *(uint2*)&sAh[r * 264 + c4 * 4] = vh;
        *(uint2*)&sAl[r * 264 + c4 * 4] = vl;
    }
    __syncthreads();

    int w = tid >> 5;
    int wm = w >> 2, wn = w & 3;
    wmma::fragment<wmma::accumulator, 16, 16, 16, float> c[2][2];
#pragma unroll
    for (int i = 0; i < 2; i++)
#pragma unroll
        for (int j = 0; j < 2; j++) wmma::fill_fragment(c[i][j], 0.f);
    const __nv_bfloat16* w2h = g_w2h + layer * 32768;
    const __nv_bfloat16* w2l = g_w2l + layer * 32768;
#pragma unroll
    for (int ks = 0; ks < 16; ks++) {
        wmma::fragment<wmma::matrix_a, 16, 16, 16, __nv_bfloat16, wmma::row_major> ah[2], al[2];
#pragma unroll
        for (int i = 0; i < 2; i++) {
            wmma::load_matrix_sync(ah[i], sAh + (wm * 32 + i * 16) * 264 + ks * 16, 264);
            wmma::load_matrix_sync(al[i], sAl + (wm * 32 + i * 16) * 264 + ks * 16, 264);
        }
#pragma unroll
        for (int j = 0; j < 2; j++) {
            int ncol = wn * 32 + j * 16;
            wmma::fragment<wmma::matrix_b, 16, 16, 16, __nv_bfloat16, wmma::col_major> bh, bl;
            wmma::load_matrix_sync(bh, w2h + ncol * 256 + ks * 16, 256);
            wmma::load_matrix_sync(bl, w2l + ncol * 256 + ks * 16, 256);
#pragma unroll
            for (int i = 0; i < 2; i++) {
                wmma::mma_sync(c[i][j], ah[i], bh, c[i][j]);
                wmma::mma_sync(c[i][j], al[i], bh, c[i][j]);
                wmma::mma_sync(c[i][j], ah[i], bl, c[i][j]);
            }
        }
    }
    __syncthreads();   // all warps done reading sA before sC overwrites it
#pragma unroll
    for (int i = 0; i < 2; i++)
#pragma unroll
        for (int j = 0; j < 2; j++)
            wmma::store_matrix_sync(sC + (wm * 32 + i * 16) * 136 + wn * 32 + j * 16,
                                    c[i][j], 136, wmma::mem_row_major);
    __syncthreads();
    for (int u = tid; u < 64 * 32; u += 256) {
        int r = u >> 5, c4 = u & 31;
        int n = n0 + r;
        float4 res = make_float4(0.f, 0.f, 0.f, 0.f);
        if (use_res && n < NN) res = *(const float4*)&g_h[n * HID + c4 * 4];
#pragma unroll
        for (int i = 0; i < 4; i++) {
            int cc = c4 * 4 + i;
            sC[r * 136 + cc] += sB[cc] + ((const float*)&res)[i];
        }
    }
    __syncthreads();
    {
        int r = tid >> 2, q = tid & 3;
        float sum = 0.f, sq = 0.f;
#pragma unroll 8
        for (int c0 = 0; c0 < 32; c0++) {
            float v = sC[r * 136 + q * 32 + c0];
            sum += v; sq = fmaf(v, v, sq);
        }
        sum += __shfl_xor_sync(0xffffffffu, sum, 1);
        sq  += __shfl_xor_sync(0xffffffffu, sq, 1);
        sum += __shfl_xor_sync(0xffffffffu, sum, 2);
        sq  += __shfl_xor_sync(0xffffffffu, sq, 2);
        if (q == 0) {
            float m = sum * (1.f / 128.f);
            sStat[r] = m;
            sStat[64 + r] = rsqrtf(sq * (1.f / 128.f) - m * m + 1e-5f);
        }
    }
    __syncthreads();
    for (int u = tid; u < 64 * 32; u += 256) {
        int r = u >> 5, c4 = u & 31;
        int n = n0 + r;
        if (n >= NN) continue;
        float4 v;
        v.x = sC[r * 136 + c4 * 4 + 0];
        v.y = sC[r * 136 + c4 * 4 + 1];
        v.z = sC[r * 136 + c4 * 4 + 2];
        v.w = sC[r * 136 + c4 * 4 + 3];
        *(float4*)&g_h[n * HID + c4 * 4] = v;
        if (write_pre) {
            float m = sStat[r], rstd = sStat[64 + r];
            float4 o;
            o.x = fmaxf((v.x - m) * rstd * sG[c4 * 4 + 0] + sBt[c4 * 4 + 0], 0.f);
            o.y = fmaxf((v.y - m) * rstd * sG[c4 * 4 + 1] + sBt[c4 * 4 + 1], 0.f);
            o.z = fmaxf((v.z - m) * rstd * sG[c4 * 4 + 2] + sBt[c4 * 4 + 2], 0.f);
            o.w = fmaxf((v.w - m) * rstd * sG[c4 * 4 + 3] + sBt[c4 * 4 + 3], 0.f);
            *(float4*)&g_nin[n * HID + c4 * 4] = o;
            uint2 hp;
            __half2 ha = __float22half2_rn(make_float2(o.x, o.y));
            __half2 hb = __float22half2_rn(make_float2(o.z, o.w));
            hp.x = *(uint32_t*)&ha; hp.y = *(uint32_t*)&hb;
            *(uint2*)&g_ninh[(size_t)n * HID + c4 * 4] = hp;
        }
    }
}

// ---------------- classifier ----------------
__global__ __launch_bounds__(256) void k_classifier(
    const float* __restrict__ gmm, const float* __restrict__ bb,
    const float* __restrict__ lw, const float* __restrict__ lbias,
    float* __restrict__ out)
{
    int lane = threadIdx.x & 31;
    int n = (blockIdx.x * 256 + threadIdx.x) >> 5;
    if (n >= NN) return;
    float4 v = ((const float4*)g_h)[n * 32 + lane];
    float s = v.x + v.y + v.z + v.w;
    float q = v.x * v.x + v.y * v.y + v.z * v.z + v.w * v.w;
#pragma unroll
    for (int off = 16; off; off >>= 1) {
        s += __shfl_xor_sync(0xffffffffu, s, off);
        q += __shfl_xor_sync(0xffffffffu, q, off);
    }
    float m = s * (1.f / 128.f);
    float var = q * (1.f / 128.f) - m * m;
    float rstd = rsqrtf(var + 1e-5f);
    float4 g4 = ((const float4*)gmm)[lane];
    float4 b4 = ((const float4*)bb)[lane];
    float h0 = fmaxf((v.x - m) * rstd * g4.x + b4.x, 0.f);
    float h1 = fmaxf((v.y - m) * rstd * g4.y + b4.y, 0.f);
    float h2 = fmaxf((v.z - m) * rstd * g4.z + b4.z, 0.f);
    float h3 = fmaxf((v.w - m) * rstd * g4.w + b4.w, 0.f);
    int c0 = lane * 4;
    float r[NCLS];
#pragma unroll
    for (int j = 0; j < NCLS; j++) {
        float p = h0 * lw[c0 * NCLS + j];
        p = fmaf(h1, lw[(c0 + 1) * NCLS + j], p);
        p = fmaf(h2, lw[(c0 + 2) * NCLS + j], p);
        p = fmaf(h3, lw[(c0 + 3) * NCLS + j], p);
#pragma unroll
        for (int off = 16; off; off >>= 1) p += __shfl_xor_sync(0xffffffffu, p, off);
        r[j] = p;
    }
#pragma unroll
    for (int j = 0; j < NCLS; j++)
        if (lane == j) out[n * NCLS + j] = r[j] + lbias[j];
}

// ---------------- launch ----------------
extern "C" void kernel_launch(void* const* d_in, const int* in_sizes, int n_in,
                              void* d_out, int out_size)
{
    const float* x         = (const float*)d_in[0];
    const float* edge_attr = (const float*)d_in[1];
    const float* node_w    = (const float*)d_in[2];
    const float* node_b    = (const float*)d_in[3];
    const float* edge_w    = (const float*)d_in[4];
    const float* edge_b    = (const float*)d_in[5];
    const float* mlp1_w    = (const float*)d_in[6];
    const float* mlp1_b    = (const float*)d_in[7];
    const float* ln_g      = (const float*)d_in[8];
    const float* ln_b      = (const float*)d_in[9];
    const float* mlp2_w    = (const float*)d_in[10];
    const float* mlp2_b    = (const float*)d_in[11];
    const float* t         = (const float*)d_in[12];
    const float* norm_g    = (const float*)d_in[13];
    const float* norm_b    = (const float*)d_in[14];
    const float* lin_w     = (const float*)d_in[15];
    const float* lin_b     = (const float*)d_in[16];
    const int*   edge_index= (const int*)d_in[17];
    const int* src = edge_index;
    const int* dst = edge_index + NE;
    float* out = (float*)d_out;

    static int attr_done = 0;
    if (!attr_done) {
        cudaFuncSetAttribute(k_wgemm1, cudaFuncAttributeMaxDynamicSharedMemorySize, G1_SMEM);
        cudaFuncSetAttribute(k_wgemm2, cudaFuncAttributeMaxDynamicSharedMemorySize, G2_SMEM);
        attr_done = 1;
    }

    // g_cnt is zero on entry (module-load zero; trailing k_zero_cnt each replay)
    k_node_enc<<<1184, 256>>>(x, node_w, node_b);                          // 0
    k_hist<<<(NE + 255) / 256, 256>>>(dst);                                // 1
    k_scan<<<1, 1024>>>();                                                 // 2
    k_encscatter<<<NE / 64, 256>>>(edge_attr, src, dst, edge_w, edge_b);   // 3 <- profiled
    k_wconv<<<384, 256>>>(mlp1_w, mlp2_w);                                 // 4

    const int GGRID = (NN + 63) / 64;   // 469
    for (int l = 0; l < 3; l++) {
        k_edge_agg<<<(NN * 32 + 255) / 256, 256>>>(l, t);
        k_wgemm1<<<GGRID, 256, G1_SMEM>>>(l, mlp1_b + l * 256,
                                          ln_g + l * 256, ln_b + l * 256);
        k_wgemm2<<<GGRID, 256, G2_SMEM>>>(l, mlp2_b + l * HID,
                                          norm_g + (l + 1) * HID, norm_b + (l + 1) * HID,
                                          l > 0, l < 2 ? 1 : 0);
    }
    k_classifier<<<(NN * 32 + 255) / 256, 256>>>(norm_g, norm_b, lin_w, lin_b, out);
    k_zero_cnt<<<(NN + 255) / 256, 256>>>();
}

// round 15
// speedup vs baseline: 1.0166x; 1.0160x over previous
#include <cuda_runtime.h>
#include <cuda_fp16.h>
#include <cuda_bf16.h>
#include <mma.h>
#include <cstdint>

using namespace nvcuda;

#define NN 30000
#define NE 480000
#define HID 128
#define F_IN 64
#define F_EDGE 16
#define NCLS 10

typedef unsigned long long ull;

__device__ __forceinline__ ull pack2(float lo, float hi) {
    ull r; asm("mov.b64 %0, {%1, %2};" : "=l"(r) : "f"(lo), "f"(hi)); return r;
}
__device__ __forceinline__ float2 unpack2(ull v) {
    float2 r; asm("mov.b64 {%0, %1}, %2;" : "=f"(r.x), "=f"(r.y) : "l"(v)); return r;
}
__device__ __forceinline__ void fma2(ull& d, ull a, ull b) {
    asm("fma.rn.f32x2 %0, %1, %2, %0;" : "+l"(d) : "l"(a), "l"(b));
}

// ---------------- device scratch ----------------
__device__ __align__(16) __half g_eah[(size_t)NE * HID];
__device__ int   g_srcs[NE];
__device__ int   g_rowptr[NN + 1];
__device__ int   g_cnt[NN];
__device__ __align__(16) float  g_h[NN * HID];
__device__ __align__(16) float  g_nin[NN * HID];
__device__ __align__(16) __half g_ninh[NN * HID];
__device__ __align__(16) __nv_bfloat16 g_zh[NN * HID];
__device__ __align__(16) __nv_bfloat16 g_zl[NN * HID];
__device__ __align__(16) __nv_bfloat16 g_midh[(size_t)NN * 256];
__device__ __align__(16) __nv_bfloat16 g_midl[(size_t)NN * 256];
__device__ __align__(16) __nv_bfloat16 g_w1h[3 * 256 * 128];   // W1^T hi: (n,k) at n*128+k
__device__ __align__(16) __nv_bfloat16 g_w1l[3 * 256 * 128];
__device__ __align__(16) __nv_bfloat16 g_w2h[3 * 128 * 256];   // W2^T hi: (n,k) at n*256+k
__device__ __align__(16) __nv_bfloat16 g_w2l[3 * 128 * 256];
__device__ __align__(16) __nv_bfloat16 g_ewh[128 * 16];        // edge W^T hi: (n,k) at n*16+k
__device__ __align__(16) __nv_bfloat16 g_ewl[128 * 16];

// ---------------- CSR build ----------------
__global__ void k_zero_cnt() {
    int i = blockIdx.x * blockDim.x + threadIdx.x;
    if (i < NN) g_cnt[i] = 0;
}

__global__ void k_hist(const int* __restrict__ dst) {
    int i = blockIdx.x * blockDim.x + threadIdx.x;
    if (i < NE) atomicAdd(&g_cnt[dst[i]], 1);
}

__global__ __launch_bounds__(1024) void k_scan() {
    __shared__ int wsum[32];
    const int CH = 30;
    int tid = threadIdx.x;
    int base = tid * CH;
    int loc[CH];
    int s = 0;
#pragma unroll
    for (int i = 0; i < CH; i++) {
        int idx = base + i;
        loc[i] = (idx < NN) ? g_cnt[idx] : 0;
        s += loc[i];
    }
    int lane = tid & 31, wid = tid >> 5;
    int v = s;
#pragma unroll
    for (int off = 1; off < 32; off <<= 1) {
        int t = __shfl_up_sync(0xffffffffu, v, off);
        if (lane >= off) v += t;
    }
    if (lane == 31) wsum[wid] = v;
    __syncthreads();
    if (wid == 0) {
        int wv = wsum[lane];
#pragma unroll
        for (int off = 1; off < 32; off <<= 1) {
            int t = __shfl_up_sync(0xffffffffu, wv, off);
            if (lane >= off) wv += t;
        }
        wsum[lane] = wv;
    }
    __syncthreads();
    int run = v - s + (wid ? wsum[wid - 1] : 0);
#pragma unroll
    for (int i = 0; i < CH; i++) {
        int idx = base + i;
        if (idx < NN) {
            g_rowptr[idx] = run;
            run += loc[i];
            g_cnt[idx] = 0;
        }
    }
    if (tid == 1023) g_rowptr[NN] = run;
}

// ---------------- weight conversion: W1^T, W2^T, edgeW^T -> bf16 hi/lo planes ----------------
__global__ __launch_bounds__(256) void k_wconv(const float* __restrict__ w1,
                                               const float* __restrict__ w2,
                                               const float* __restrict__ ew)
{
    int i = blockIdx.x * 256 + threadIdx.x;
    if (i < 3 * 256 * 128) {
        int l = i >> 15, rem = i & 32767;
        int n = rem >> 7, k = rem & 127;
        float v = w1[l * 32768 + k * 256 + n];
        __nv_bfloat16 hi = __float2bfloat16(v);
        g_w1h[i] = hi;
        g_w1l[i] = __float2bfloat16(v - __bfloat162float(hi));

        int n2 = rem >> 8, k2 = rem & 255;
        float v2 = w2[l * 32768 + k2 * 128 + n2];
        __nv_bfloat16 hi2 = __float2bfloat16(v2);
        g_w2h[i] = hi2;
        g_w2l[i] = __float2bfloat16(v2 - __bfloat162float(hi2));
    }
    if (i < 128 * 16) {   // edge W^T: (n,k) <- ew[k*128+n]
        int n = i >> 4, k = i & 15;
        float v = ew[k * 128 + n];
        __nv_bfloat16 hi = __float2bfloat16(v);
        g_ewh[i] = hi;
        g_ewl[i] = __float2bfloat16(v - __bfloat162float(hi));
    }
}

// ---------------- fused edge encoder + scatter (wmma): 64 edges/block ----------------
__global__ __launch_bounds__(256) void k_encscatter(
    const float* __restrict__ edge_attr, const int* __restrict__ src,
    const int* __restrict__ dst,
    const float* __restrict__ bias)
{
    __shared__ __align__(16) __nv_bfloat16 sAh[64 * 24];   // 64x16 attrs hi, ldm 24
    __shared__ __align__(16) __nv_bfloat16 sAl[64 * 24];
    __shared__ __align__(16) float sC[64 * 136];           // fp32 result tile
    __shared__ int sPos[64];
    __shared__ float sBias[HID];
    int p0 = blockIdx.x * 64;
    int tid = threadIdx.x;
    if (tid < 64) {
        int e = p0 + tid;
        int d = dst[e];
        int rank = atomicAdd(&g_cnt[d], 1);
        int pos = g_rowptr[d] + rank;
        sPos[tid] = pos;
        g_srcs[pos] = src[e];
    }
    if (tid < HID) sBias[tid] = bias[tid];
    for (int i = tid; i < 64 * F_EDGE; i += 256) {
        int r = i >> 4, k = i & 15;
        float v = edge_attr[(size_t)(p0 + r) * F_EDGE + k];
        __nv_bfloat16 hi = __float2bfloat16(v);
        sAh[r * 24 + k] = hi;
        sAl[r * 24 + k] = __float2bfloat16(v - __bfloat162float(hi));
    }
    __syncthreads();

    int w = tid >> 5;
    int wm = w & 3;            // m-tile (16 edges)
    int wg = w >> 2;           // n-group (0/1): n-tiles wg*4 .. wg*4+3
    wmma::fragment<wmma::matrix_a, 16, 16, 16, __nv_bfloat16, wmma::row_major> ah, al;
    wmma::load_matrix_sync(ah, sAh + wm * 16 * 24, 24);
    wmma::load_matrix_sync(al, sAl + wm * 16 * 24, 24);
#pragma unroll
    for (int j = 0; j < 4; j++) {
        int ncol = (wg * 4 + j) * 16;
        wmma::fragment<wmma::matrix_b, 16, 16, 16, __nv_bfloat16, wmma::col_major> bh, bl;
        wmma::load_matrix_sync(bh, g_ewh + ncol * 16, 16);
        wmma::load_matrix_sync(bl, g_ewl + ncol * 16, 16);
        wmma::fragment<wmma::accumulator, 16, 16, 16, float> c;
        wmma::fill_fragment(c, 0.f);
        wmma::mma_sync(c, ah, bh, c);
        wmma::mma_sync(c, al, bh, c);
        wmma::mma_sync(c, ah, bl, c);
        wmma::store_matrix_sync(sC + wm * 16 * 136 + ncol, c, 136, wmma::mem_row_major);
    }
    __syncthreads();
    // epilogue: +bias, cvt fp16, scatter rows to dst-sorted positions
    for (int u = tid; u < 64 * 32; u += 256) {
        int r = u >> 5, c4 = u & 31;
        float v0 = sC[r * 136 + c4 * 4 + 0] + sBias[c4 * 4 + 0];
        float v1 = sC[r * 136 + c4 * 4 + 1] + sBias[c4 * 4 + 1];
        float v2 = sC[r * 136 + c4 * 4 + 2] + sBias[c4 * 4 + 2];
        float v3 = sC[r * 136 + c4 * 4 + 3] + sBias[c4 * 4 + 3];
        __half2 ha = __float22half2_rn(make_float2(v0, v1));
        __half2 hb = __float22half2_rn(make_float2(v2, v3));
        uint2 pv;
        pv.x = *(uint32_t*)&ha;
        pv.y = *(uint32_t*)&hb;
        *(uint2*)&g_eah[(size_t)sPos[r] * HID + c4 * 4] = pv;
    }
}

// ---------------- node encoder ----------------
__global__ __launch_bounds__(256) void k_node_enc(
    const float* __restrict__ x, const float* __restrict__ W, const float* __restrict__ bias)
{
    __shared__ __align__(16) float sW[F_IN * HID];
    __shared__ __align__(16) float sB[HID];
    for (int i = threadIdx.x; i < F_IN * HID; i += 256) sW[i] = W[i];
    if (threadIdx.x < HID) sB[threadIdx.x] = bias[threadIdx.x];
    __syncthreads();
    int lane = threadIdx.x & 31;
    int warp = (blockIdx.x * 256 + threadIdx.x) >> 5;
    int nw = gridDim.x * 8;
    float4 bv = ((float4*)sB)[lane];
    for (int n = warp; n < NN; n += nw) {
        float a0 = x[n * F_IN + lane];
        float a1 = x[n * F_IN + 32 + lane];
        float4 acc = bv;
#pragma unroll
        for (int k = 0; k < F_IN; k++) {
            float ak = __shfl_sync(0xffffffffu, (k < 32) ? a0 : a1, k & 31);
            float4 w = ((const float4*)(sW + k * HID))[lane];
            acc.x = fmaf(ak, w.x, acc.x);
            acc.y = fmaf(ak, w.y, acc.y);
            acc.z = fmaf(ak, w.z, acc.z);
            acc.w = fmaf(ak, w.w, acc.w);
        }
        ((float4*)g_h)[n * 32 + lane] = acc;
        __half2 h0 = __float22half2_rn(make_float2(acc.x, acc.y));
        __half2 h1 = __float22half2_rn(make_float2(acc.z, acc.w));
        *(__half2*)&g_ninh[(size_t)n * HID + 4 * lane]     = h0;
        *(__half2*)&g_ninh[(size_t)n * HID + 4 * lane + 2] = h1;
    }
}

// ---------------- edge aggregation ----------------
__device__ __forceinline__ float4 load_h16(const __half* base, size_t row, int lane) {
    uint2 raw = *(const uint2*)(base + row * HID + lane * 4);
    float2 fa = __half22float2(*(__half2*)&raw.x);
    float2 fb = __half22float2(*(__half2*)&raw.y);
    return make_float4(fa.x, fa.y, fb.x, fb.y);
}

__global__ __launch_bounds__(256) void k_edge_agg(int layer, const float* __restrict__ t_arr)
{
    int lane = threadIdx.x & 31;
    int n = (blockIdx.x * 256 + threadIdx.x) >> 5;
    if (n >= NN) return;
    const float4* x4 = (const float4*)((layer == 0) ? g_h : g_nin);
    float tv = t_arr[layer];
    int p = g_rowptr[n], end = g_rowptr[n + 1];
    float4 sa = make_float4(0.f, 0.f, 0.f, 0.f), wa = sa;
    float4 sb = sa, wb = sa;
    for (; p + 4 <= end; p += 4) {
        int s0 = g_srcs[p], s1 = g_srcs[p + 1], s2 = g_srcs[p + 2], s3 = g_srcs[p + 3];
        float4 e0 = load_h16(g_eah, p, lane);
        float4 e1 = load_h16(g_eah, p + 1, lane);
        float4 e2 = load_h16(g_eah, p + 2, lane);
        float4 e3 = load_h16(g_eah, p + 3, lane);
        float4 h0 = load_h16(g_ninh, s0, lane);
        float4 h1 = load_h16(g_ninh, s1, lane);
        float4 h2 = load_h16(g_ninh, s2, lane);
        float4 h3 = load_h16(g_ninh, s3, lane);
#define DO_EDGE(hh, ee, S, W) { \
        float m0 = fmaxf(hh.x + ee.x, 0.f) + 1e-7f; \
        float m1 = fmaxf(hh.y + ee.y, 0.f) + 1e-7f; \
        float m2 = fmaxf(hh.z + ee.z, 0.f) + 1e-7f; \
        float m3 = fmaxf(hh.w + ee.w, 0.f) + 1e-7f; \
        float x0 = __expf(m0 * tv), x1 = __expf(m1 * tv); \
        float x2 = __expf(m2 * tv), x3 = __expf(m3 * tv); \
        S.x += x0; S.y += x1; S.z += x2; S.w += x3; \
        W.x = fmaf(m0, x0, W.x); W.y = fmaf(m1, x1, W.y); \
        W.z = fmaf(m2, x2, W.z); W.w = fmaf(m3, x3, W.w); }
        DO_EDGE(h0, e0, sa, wa);
        DO_EDGE(h1, e1, sb, wb);
        DO_EDGE(h2, e2, sa, wa);
        DO_EDGE(h3, e3, sb, wb);
    }
    for (; p < end; p++) {
        int s0 = g_srcs[p];
        float4 e0 = load_h16(g_eah, p, lane);
        float4 h0 = load_h16(g_ninh, s0, lane);
        DO_EDGE(h0, e0, sa, wa);
    }
#undef DO_EDGE
    sa.x += sb.x; sa.y += sb.y; sa.z += sb.z; sa.w += sb.w;
    wa.x += wb.x; wa.y += wb.y; wa.z += wb.z; wa.w += wb.w;
    float4 xr = x4[n * 32 + lane];
    float z[4];
    z[0] = wa.x / (sa.x + 1e-16f) + xr.x;
    z[1] = wa.y / (sa.y + 1e-16f) + xr.y;
    z[2] = wa.z / (sa.z + 1e-16f) + xr.z;
    z[3] = wa.w / (sa.w + 1e-16f) + xr.w;
    ushort hh[4], ll[4];
#pragma unroll
    for (int i = 0; i < 4; i++) {
        __nv_bfloat16 hi = __float2bfloat16(z[i]);
        __nv_bfloat16 lo = __float2bfloat16(z[i] - __bfloat162float(hi));
        hh[i] = __bfloat16_as_ushort(hi);
        ll[i] = __bfloat16_as_ushort(lo);
    }
    uint2 ph, pl;
    ph.x = (uint32_t)hh[0] | ((uint32_t)hh[1] << 16);
    ph.y = (uint32_t)hh[2] | ((uint32_t)hh[3] << 16);
    pl.x = (uint32_t)ll[0] | ((uint32_t)ll[1] << 16);
    pl.y = (uint32_t)ll[2] | ((uint32_t)ll[3] << 16);
    *(uint2*)&g_zh[(size_t)n * HID + 4 * lane] = ph;
    *(uint2*)&g_zl[(size_t)n * HID + 4 * lane] = pl;
}

// ---------------- GEMM1 (wmma): mid = relu(LN(z @ W1 + b1)), tile 64x256, smem union ----------------
#define G1_SMEM (67584 + 512)
__global__ __launch_bounds__(256) void k_wgemm1(
    int layer, const float* __restrict__ b1,
    const float* __restrict__ lg, const float* __restrict__ lb)
{
    extern __shared__ char smem[];
    __nv_bfloat16* sAh = (__nv_bfloat16*)smem;
    __nv_bfloat16* sAl = (__nv_bfloat16*)(smem + 17408);
    float* sC = (float*)smem;                       // UNION with sAh/sAl
    float* sStat = (float*)(smem + 67584);
    __shared__ float sB[256], sG[256], sBt[256];
    int tid = threadIdx.x;
    int n0 = blockIdx.x * 64;
    if (tid < 256) { sB[tid] = b1[tid]; sG[tid] = lg[tid]; sBt[tid] = lb[tid]; }
    for (int u = tid; u < 64 * 32; u += 256) {
        int r = u >> 5, c4 = u & 31;
        int n = n0 + r;
        uint2 vh = make_uint2(0u, 0u), vl = vh;
        if (n < NN) {
            vh = *(const uint2*)&g_zh[(size_t)n * HID + c4 * 4];
            vl = *(const uint2*)&g_zl[(size_t)n * HID + c4 * 4];
        }
        *(uint2*)&sAh[r * 136 + c4 * 4] = vh;
        *(uint2*)&sAl[r * 136 + c4 * 4] = vl;
    }
    __syncthreads();

    int w = tid >> 5;
    int wm = w >> 2, wn = w & 3;
    wmma::fragment<wmma::accumulator, 16, 16, 16, float> c[2][4];
#pragma unroll
    for (int i = 0; i < 2; i++)
#pragma unroll
        for (int j = 0; j < 4; j++) wmma::fill_fragment(c[i][j], 0.f);
    const __nv_bfloat16* w1h = g_w1h + layer * 32768;
    const __nv_bfloat16* w1l = g_w1l + layer * 32768;
#pragma unroll
    for (int ks = 0; ks < 8; ks++) {
        wmma::fragment<wmma::matrix_a, 16, 16, 16, __nv_bfloat16, wmma::row_major> ah[2], al[2];
#pragma unroll
        for (int i = 0; i < 2; i++) {
            wmma::load_matrix_sync(ah[i], sAh + (wm * 32 + i * 16) * 136 + ks * 16, 136);
            wmma::load_matrix_sync(al[i], sAl + (wm * 32 + i * 16) * 136 + ks * 16, 136);
        }
#pragma unroll
        for (int j = 0; j < 4; j++) {
            int ncol = wn * 64 + j * 16;
            wmma::fragment<wmma::matrix_b, 16, 16, 16, __nv_bfloat16, wmma::col_major> bh, bl;
            wmma::load_matrix_sync(bh, w1h + ncol * 128 + ks * 16, 128);
            wmma::load_matrix_sync(bl, w1l + ncol * 128 + ks * 16, 128);
#pragma unroll
            for (int i = 0; i < 2; i++) {
                wmma::mma_sync(c[i][j], ah[i], bh, c[i][j]);
                wmma::mma_sync(c[i][j], al[i], bh, c[i][j]);
                wmma::mma_sync(c[i][j], ah[i], bl, c[i][j]);
            }
        }
    }
    __syncthreads();   // all warps done reading sA before sC overwrites it
#pragma unroll
    for (int i = 0; i < 2; i++)
#pragma unroll
        for (int j = 0; j < 4; j++)
            wmma::store_matrix_sync(sC + (wm * 32 + i * 16) * 264 + wn * 64 + j * 16,
                                    c[i][j], 264, wmma::mem_row_major);
    __syncthreads();
    {
        int r = tid >> 2, q = tid & 3;
        float sum = 0.f, sq = 0.f;
#pragma unroll 8
        for (int c0 = 0; c0 < 64; c0++) {
            float v = sC[r * 264 + q * 64 + c0] + sB[q * 64 + c0];
            sum += v; sq = fmaf(v, v, sq);
        }
        sum += __shfl_xor_sync(0xffffffffu, sum, 1);
        sq  += __shfl_xor_sync(0xffffffffu, sq, 1);
        sum += __shfl_xor_sync(0xffffffffu, sum, 2);
        sq  += __shfl_xor_sync(0xffffffffu, sq, 2);
        if (q == 0) {
            float m = sum * (1.f / 256.f);
            sStat[r] = m;
            sStat[64 + r] = rsqrtf(sq * (1.f / 256.f) - m * m + 1e-5f);
        }
    }
    __syncthreads();
    for (int u = tid; u < 64 * 64; u += 256) {
        int r = u >> 6, c4 = u & 63;
        int n = n0 + r;
        if (n >= NN) continue;
        float m = sStat[r], rstd = sStat[64 + r];
        ushort hh[4], ll[4];
#pragma unroll
        for (int i = 0; i < 4; i++) {
            int cc = c4 * 4 + i;
            float v = sC[r * 264 + cc] + sB[cc];
            float o = fmaxf((v - m) * rstd * sG[cc] + sBt[cc], 0.f);
            __nv_bfloat16 hi = __float2bfloat16(o);
            __nv_bfloat16 lo = __float2bfloat16(o - __bfloat162float(hi));
            hh[i] = __bfloat16_as_ushort(hi);
            ll[i] = __bfloat16_as_ushort(lo);
        }
        uint2 vh, vl;
        vh.x = (uint32_t)hh[0] | ((uint32_t)hh[1] << 16);
        vh.y = (uint32_t)hh[2] | ((uint32_t)hh[3] << 16);
        vl.x = (uint32_t)ll[0] | ((uint32_t)ll[1] << 16);
        vl.y = (uint32_t)ll[2] | ((uint32_t)ll[3] << 16);
        *(uint2*)&g_midh[(size_t)n * 256 + c4 * 4] = vh;
        *(uint2*)&g_midl[(size_t)n * 256 + c4 * 4] = vl;
    }
}

// ---------------- GEMM2 (wmma): h = mid @ W2 + b2 (+res); fused prenorm. tile 64x128, smem union ----------------
#define G2_SMEM (67584 + 512)
__global__ __launch_bounds__(256) void k_wgemm2(
    int layer, const float* __restrict__ b2,
    const float* __restrict__ gn, const float* __restrict__ bn,
    int use_res, int write_pre)
{
    extern __shared__ char smem[];
    __nv_bfloat16* sAh = (__nv_bfloat16*)smem;
    __nv_bfloat16* sAl = (__nv_bfloat16*)(smem + 33792);
    float* sC = (float*)smem;                       // UNION with sAh
    float* sStat = (float*)(smem + 67584);
    __shared__ float sB[128], sG[128], sBt[128];
    int tid = threadIdx.x;
    int n0 = blockIdx.x * 64;
    if (tid < 128) { sB[tid] = b2[tid]; sG[tid] = gn[tid]; sBt[tid] = bn[tid]; }
    for (int u = tid; u < 64 * 64; u += 256) {
        int r = u >> 6, c4 = u & 63;
        int n = n0 + r;
        uint2 vh = make_uint2(0u, 0u), vl = vh;
        if (n < NN) {
            vh = *(const uint2*)&g_midh[(size_t)n * 256 + c4 * 4];
            vl = *(const uint2*)&g_midl[(size_t)n * 256 + c4 * 4];
        }
        *(uint2*)&sAh[r * 264 + c4 * 4] = vh;
        *(uint2*)&sAl[r * 264 + c4 * 4] = vl;
    }
    __syncthreads();

    int w = tid >> 5;
    int wm = w >> 2, wn = w & 3;
    wmma::fragment<wmma::accumulator, 16, 16, 16, float> c[2][2];
#pragma unroll
    for (int i = 0; i < 2; i++)
#pragma unroll
        for (int j = 0; j < 2; j++) wmma::fill_fragment(c[i][j], 0.f);
    const __nv_bfloat16* w2h = g_w2h + layer * 32768;
    const __nv_bfloat16* w2l = g_w2l + layer * 32768;
#pragma unroll
    for (int ks = 0; ks < 16; ks++) {
        wmma::fragment<wmma::matrix_a, 16, 16, 16, __nv_bfloat16, wmma::row_major> ah[2], al[2];
#pragma unroll
        for (int i = 0; i < 2; i++) {
            wmma::load_matrix_sync(ah[i], sAh + (wm * 32 + i * 16) * 264 + ks * 16, 264);
            wmma::load_matrix_sync(al[i], sAl + (wm * 32 + i * 16) * 264 + ks * 16, 264);
        }
#pragma unroll
        for (int j = 0; j < 2; j++) {
            int ncol = wn * 32 + j * 16;
            wmma::fragment<wmma::matrix_b, 16, 16, 16, __nv_bfloat16, wmma::col_major> bh, bl;
            wmma::load_matrix_sync(bh, w2h + ncol * 256 + ks * 16, 256);
            wmma::load_matrix_sync(bl, w2l + ncol * 256 + ks * 16, 256);
#pragma unroll
            for (int i = 0; i < 2; i++) {
                wmma::mma_sync(c[i][j], ah[i], bh, c[i][j]);
                wmma::mma_sync(c[i][j], al[i], bh, c[i][j]);
                wmma::mma_sync(c[i][j], ah[i], bl, c[i][j]);
            }
        }
    }
    __syncthreads();   // all warps done reading sA before sC overwrites it
#pragma unroll
    for (int i = 0; i < 2; i++)
#pragma unroll
        for (int j = 0; j < 2; j++)
            wmma::store_matrix_sync(sC + (wm * 32 + i * 16) * 136 + wn * 32 + j * 16,
                                    c[i][j], 136, wmma::mem_row_major);
    __syncthreads();
    for (int u = tid; u < 64 * 32; u += 256) {
        int r = u >> 5, c4 = u & 31;
        int n = n0 + r;
        float4 res = make_float4(0.f, 0.f, 0.f, 0.f);
        if (use_res && n < NN) res = *(const float4*)&g_h[n * HID + c4 * 4];
#pragma unroll
        for (int i = 0; i < 4; i++) {
            int cc = c4 * 4 + i;
            sC[r * 136 + cc] += sB[cc] + ((const float*)&res)[i];
        }
    }
    __syncthreads();
    {
        int r = tid >> 2, q = tid & 3;
        float sum = 0.f, sq = 0.f;
#pragma unroll 8
        for (int c0 = 0; c0 < 32; c0++) {
            float v = sC[r * 136 + q * 32 + c0];
            sum += v; sq = fmaf(v, v, sq);
        }
        sum += __shfl_xor_sync(0xffffffffu, sum, 1);
        sq  += __shfl_xor_sync(0xffffffffu, sq, 1);
        sum += __shfl_xor_sync(0xffffffffu, sum, 2);
        sq  += __shfl_xor_sync(0xffffffffu, sq, 2);
        if (q == 0) {
            float m = sum * (1.f / 128.f);
            sStat[r] = m;
            sStat[64 + r] = rsqrtf(sq * (1.f / 128.f) - m * m + 1e-5f);
        }
    }
    __syncthreads();
    for (int u = tid; u < 64 * 32; u += 256) {
        int r = u >> 5, c4 = u & 31;
        int n = n0 + r;
        if (n >= NN) continue;
        float4 v;
        v.x = sC[r * 136 + c4 * 4 + 0];
        v.y = sC[r * 136 + c4 * 4 + 1];
        v.z = sC[r * 136 + c4 * 4 + 2];
        v.w = sC[r * 136 + c4 * 4 + 3];
        *(float4*)&g_h[n * HID + c4 * 4] = v;
        if (write_pre) {
            float m = sStat[r], rstd = sStat[64 + r];
            float4 o;
            o.x = fmaxf((v.x - m) * rstd * sG[c4 * 4 + 0] + sBt[c4 * 4 + 0], 0.f);
            o.y = fmaxf((v.y - m) * rstd * sG[c4 * 4 + 1] + sBt[c4 * 4 + 1], 0.f);
            o.z = fmaxf((v.z - m) * rstd * sG[c4 * 4 + 2] + sBt[c4 * 4 + 2], 0.f);
            o.w = fmaxf((v.w - m) * rstd * sG[c4 * 4 + 3] + sBt[c4 * 4 + 3], 0.f);
            *(float4*)&g_nin[n * HID + c4 * 4] = o;
            uint2 hp;
            __half2 ha = __float22half2_rn(make_float2(o.x, o.y));
            __half2 hb = __float22half2_rn(make_float2(o.z, o.w));
            hp.x = *(uint32_t*)&ha; hp.y = *(uint32_t*)&hb;
            *(uint2*)&g_ninh[(size_t)n * HID + c4 * 4] = hp;
        }
    }
}

// ---------------- classifier ----------------
__global__ __launch_bounds__(256) void k_classifier(
    const float* __restrict__ gmm, const float* __restrict__ bb,
    const float* __restrict__ lw, const float* __restrict__ lbias,
    float* __restrict__ out)
{
    int lane = threadIdx.x & 31;
    int n = (blockIdx.x * 256 + threadIdx.x) >> 5;
    if (n >= NN) return;
    float4 v = ((const float4*)g_h)[n * 32 + lane];
    float s = v.x + v.y + v.z + v.w;
    float q = v.x * v.x + v.y * v.y + v.z * v.z + v.w * v.w;
#pragma unroll
    for (int off = 16; off; off >>= 1) {
        s += __shfl_xor_sync(0xffffffffu, s, off);
        q += __shfl_xor_sync(0xffffffffu, q, off);
    }
    float m = s * (1.f / 128.f);
    float var = q * (1.f / 128.f) - m * m;
    float rstd = rsqrtf(var + 1e-5f);
    float4 g4 = ((const float4*)gmm)[lane];
    float4 b4 = ((const float4*)bb)[lane];
    float h0 = fmaxf((v.x - m) * rstd * g4.x + b4.x, 0.f);
    float h1 = fmaxf((v.y - m) * rstd * g4.y + b4.y, 0.f);
    float h2 = fmaxf((v.z - m) * rstd * g4.z + b4.z, 0.f);
    float h3 = fmaxf((v.w - m) * rstd * g4.w + b4.w, 0.f);
    int c0 = lane * 4;
    float r[NCLS];
#pragma unroll
    for (int j = 0; j < NCLS; j++) {
        float p = h0 * lw[c0 * NCLS + j];
        p = fmaf(h1, lw[(c0 + 1) * NCLS + j], p);
        p = fmaf(h2, lw[(c0 + 2) * NCLS + j], p);
        p = fmaf(h3, lw[(c0 + 3) * NCLS + j], p);
#pragma unroll
        for (int off = 16; off; off >>= 1) p += __shfl_xor_sync(0xffffffffu, p, off);
        r[j] = p;
    }
#pragma unroll
    for (int j = 0; j < NCLS; j++)
        if (lane == j) out[n * NCLS + j] = r[j] + lbias[j];
}

// ---------------- launch ----------------
extern "C" void kernel_launch(void* const* d_in, const int* in_sizes, int n_in,
                              void* d_out, int out_size)
{
    const float* x         = (const float*)d_in[0];
    const float* edge_attr = (const float*)d_in[1];
    const float* node_w    = (const float*)d_in[2];
    const float* node_b    = (const float*)d_in[3];
    const float* edge_w    = (const float*)d_in[4];
    const float* edge_b    = (const float*)d_in[5];
    const float* mlp1_w    = (const float*)d_in[6];
    const float* mlp1_b    = (const float*)d_in[7];
    const float* ln_g      = (const float*)d_in[8];
    const float* ln_b      = (const float*)d_in[9];
    const float* mlp2_w    = (const float*)d_in[10];
    const float* mlp2_b    = (const float*)d_in[11];
    const float* t         = (const float*)d_in[12];
    const float* norm_g    = (const float*)d_in[13];
    const float* norm_b    = (const float*)d_in[14];
    const float* lin_w     = (const float*)d_in[15];
    const float* lin_b     = (const float*)d_in[16];
    const int*   edge_index= (const int*)d_in[17];
    const int* src = edge_index;
    const int* dst = edge_index + NE;
    float* out = (float*)d_out;

    static int attr_done = 0;
    if (!attr_done) {
        cudaFuncSetAttribute(k_wgemm1, cudaFuncAttributeMaxDynamicSharedMemorySize, G1_SMEM);
        cudaFuncSetAttribute(k_wgemm2, cudaFuncAttributeMaxDynamicSharedMemorySize, G2_SMEM);
        attr_done = 1;
    }

    // g_cnt is zero on entry (module-load zero; trailing k_zero_cnt each replay)
    k_node_enc<<<1184, 256>>>(x, node_w, node_b);                          // 0
    k_hist<<<(NE + 255) / 256, 256>>>(dst);                                // 1
    k_scan<<<1, 1024>>>();                                                 // 2
    k_wconv<<<384, 256>>>(mlp1_w, mlp2_w, edge_w);                         // 3 (produces g_ewh/g_ewl)
    k_encscatter<<<NE / 64, 256>>>(edge_attr, src, dst, edge_b);           // 4

    const int GGRID = (NN + 63) / 64;   // 469
    for (int l = 0; l < 3; l++) {
        k_edge_agg<<<(NN * 32 + 255) / 256, 256>>>(l, t);
        k_wgemm1<<<GGRID, 256, G1_SMEM>>>(l, mlp1_b + l * 256,
                                          ln_g + l * 256, ln_b + l * 256);
        k_wgemm2<<<GGRID, 256, G2_SMEM>>>(l, mlp2_b + l * HID,
                                          norm_g + (l + 1) * HID, norm_b + (l + 1) * HID,
                                          l > 0, l < 2 ? 1 : 0);
    }
    k_classifier<<<(NN * 32 + 255) / 256, 256>>>(norm_g, norm_b, lin_w, lin_b, out);
    k_zero_cnt<<<(NN + 255) / 256, 256>>>();
}